// round 5
// baseline (speedup 1.0000x reference)
#include <cuda_runtime.h>
#include <cuda.h>
#include <cuda_fp16.h>
#include <cstdint>

// ===========================================================================
// LinearToeplitz: out[b,o] = sum_i x[b,i] * p[(O-1-o)+i] + bias[o]
// B=8192, I=O=4096.  fp16 mma.sync (HMMA) GEMM, fp32 accumulate.
// R5: 512 threads (16 warps, 4x4 warp grid, 32x64 warp tile) -> 4 warps/SMSP
//     to hide LDSM->HMMA latency; tile/pipeline unchanged (128x256x64, 3stg).
// ===========================================================================

#define BATCH_SZ 8192
#define IFEAT    4096
#define OFEAT    4096
#define BM 128
#define BN 256
#define BK 64
#define KITERS (IFEAT / BK)       // 64
#define NTHREADS 512
#define STAGES 3
#define STAGE_BYTES 49152u        // A 16KB + B 32KB
#define SMEM_TOTAL (STAGES * STAGE_BYTES)   // 147456

// ------------------------- scratch (static device) -------------------------
__device__ __half g_xh[33554432];   // 64 MB  [8192][4096] fp16 x
__device__ __half g_wh[16777216];   // 32 MB  [4096][4096] fp16 Toeplitz W

// ------------------------- asm helpers -------------------------
__device__ __forceinline__ uint32_t smem_to_u32(const void* p) {
    uint32_t a;
    asm("{ .reg .u64 t; cvta.to.shared.u64 t, %1; cvt.u32.u64 %0, t; }" : "=r"(a) : "l"(p));
    return a;
}
#define CP_ASYNC16(dst, src) \
    asm volatile("cp.async.cg.shared.global [%0], [%1], 16;" :: "r"(dst), "l"(src) : "memory")
#define CP_COMMIT() asm volatile("cp.async.commit_group;" ::: "memory")
#define CP_WAIT1()  asm volatile("cp.async.wait_group 1;" ::: "memory")

#define LDSM4(r0, r1, r2, r3, addr) \
    asm volatile("ldmatrix.sync.aligned.m8n8.x4.shared.b16 {%0,%1,%2,%3}, [%4];" \
        : "=r"(r0), "=r"(r1), "=r"(r2), "=r"(r3) : "r"(addr))

#define MMA16816(d, a, b0, b1) \
    asm volatile("mma.sync.aligned.m16n8k16.row.col.f32.f16.f16.f32 " \
        "{%0,%1,%2,%3},{%4,%5,%6,%7},{%8,%9},{%0,%1,%2,%3};" \
        : "+f"((d)[0]), "+f"((d)[1]), "+f"((d)[2]), "+f"((d)[3]) \
        : "r"((a)[0]), "r"((a)[1]), "r"((a)[2]), "r"((a)[3]), "r"(b0), "r"(b1))

// ------------------------- prep kernels -------------------------
__global__ void prep_x_kernel(const float* __restrict__ x, __half* __restrict__ xh) {
    size_t i = ((size_t)blockIdx.x * blockDim.x + threadIdx.x) * 8;
    float4 v0 = *reinterpret_cast<const float4*>(x + i);
    float4 v1 = *reinterpret_cast<const float4*>(x + i + 4);
    __half2 h[4];
    h[0] = __floats2half2_rn(v0.x, v0.y);
    h[1] = __floats2half2_rn(v0.z, v0.w);
    h[2] = __floats2half2_rn(v1.x, v1.y);
    h[3] = __floats2half2_rn(v1.z, v1.w);
    *reinterpret_cast<uint4*>(xh + i) = *reinterpret_cast<uint4*>(h);
}

// W[o][i] = p[(OFEAT-1-o) + i] : row o is a contiguous slice of p (p is ~32KB,
// L2/L1 resident). Writes fully coalesced 16B.
__global__ void prep_w_kernel(const float* __restrict__ p, __half* __restrict__ wh) {
    int o = blockIdx.x;
    const float* row = p + (OFEAT - 1 - o);
    size_t base = (size_t)o * IFEAT;
    for (int c0 = threadIdx.x * 8; c0 < IFEAT; c0 += blockDim.x * 8) {
        __half2 h[4];
        #pragma unroll
        for (int j = 0; j < 4; ++j)
            h[j] = __floats2half2_rn(__ldg(row + c0 + 2*j), __ldg(row + c0 + 2*j + 1));
        *reinterpret_cast<uint4*>(wh + base + c0) = *reinterpret_cast<uint4*>(h);
    }
}

// ------------------------- GEMM kernel -------------------------
__device__ __forceinline__ void load_stage(uint32_t sb_u32, int slot, int kt, int tid,
                                           const __half* __restrict__ xh,
                                           const __half* __restrict__ wh,
                                           int m0, int n0) {
    const uint32_t sA = sb_u32 + (uint32_t)slot * STAGE_BYTES;
    const uint32_t sB = sA + 16384u;
    const char* gA = reinterpret_cast<const char*>(xh) + ((size_t)m0 * IFEAT + kt * BK) * 2;
    const char* gB = reinterpret_cast<const char*>(wh) + ((size_t)n0 * IFEAT + kt * BK) * 2;
    // A: 128 rows x 128B = 1024 x 16B chunks
    #pragma unroll
    for (int it = 0; it < 2; ++it) {
        int chunk = tid + it * NTHREADS;
        int row = chunk >> 3;
        uint32_t cseg = (chunk & 7) << 4;
        uint32_t dst = sA + (uint32_t)row * 128 + (cseg ^ ((row & 7) << 4));
        CP_ASYNC16(dst, gA + (size_t)row * (IFEAT * 2) + cseg);
    }
    // B: 256 rows x 128B = 2048 x 16B chunks
    #pragma unroll
    for (int it = 0; it < 4; ++it) {
        int chunk = tid + it * NTHREADS;
        int row = chunk >> 3;
        uint32_t cseg = (chunk & 7) << 4;
        uint32_t dst = sB + (uint32_t)row * 128 + (cseg ^ ((row & 7) << 4));
        CP_ASYNC16(dst, gB + (size_t)row * (IFEAT * 2) + cseg);
    }
}

__global__ void __launch_bounds__(NTHREADS, 1) toep_gemm_kernel(
    const __half* __restrict__ xh,
    const __half* __restrict__ wh,
    const float* __restrict__ bias,
    float* __restrict__ out)
{
    extern __shared__ __align__(1024) char smem[];
    const uint32_t sb = smem_to_u32(smem);
    const int tid  = threadIdx.x;
    const int wid  = tid >> 5;
    const int lane = tid & 31;

    const int m0 = blockIdx.y * BM;
    const int n0 = blockIdx.x * BN;

    const int warp_m = wid & 3;    // 4 warps over M (32 rows each)
    const int warp_n = wid >> 2;   // 4 warps over N (64 cols each)

    // ldmatrix per-thread addressing
    const int aRow = warp_m * 32 + (lane & 15);
    const uint32_t aXor = (uint32_t)(aRow & 7) << 4;
    const uint32_t aCol = (uint32_t)(lane >> 4) << 4;       // 0 or 16
    const int bRow = warp_n * 64 + (lane & 7) + ((lane & 16) >> 1);
    const uint32_t bXor = (uint32_t)(bRow & 7) << 4;
    const uint32_t bCol = (uint32_t)(lane & 8) << 1;        // 0 or 16

    float acc[2][8][4];
    #pragma unroll
    for (int mi = 0; mi < 2; ++mi)
        #pragma unroll
        for (int t = 0; t < 8; ++t)
            #pragma unroll
            for (int c = 0; c < 4; ++c) acc[mi][t][c] = 0.0f;

    // prologue: 2 stages in flight
    load_stage(sb, 0, 0, tid, xh, wh, m0, n0); CP_COMMIT();
    load_stage(sb, 1, 1, tid, xh, wh, m0, n0); CP_COMMIT();

    for (int kt = 0; kt < KITERS; ++kt) {
        CP_WAIT1();
        __syncthreads();

        // issue next stage (slot kt+2 mod 3) while computing current
        if (kt + 2 < KITERS)
            load_stage(sb, (kt + 2) % STAGES, kt + 2, tid, xh, wh, m0, n0);
        CP_COMMIT();

        const uint32_t sA = sb + (uint32_t)(kt % STAGES) * STAGE_BYTES;
        const uint32_t sB = sA + 16384u;
        #pragma unroll
        for (int kk = 0; kk < 4; ++kk) {
            const uint32_t kb = (uint32_t)kk * 32;
            uint32_t a[2][4], b[4][4];
            #pragma unroll
            for (int mi = 0; mi < 2; ++mi) {
                uint32_t ad = sA + (uint32_t)(aRow + mi * 16) * 128 + ((kb + aCol) ^ aXor);
                LDSM4(a[mi][0], a[mi][1], a[mi][2], a[mi][3], ad);
            }
            #pragma unroll
            for (int nj = 0; nj < 4; ++nj) {
                uint32_t bd = sB + (uint32_t)(bRow + nj * 16) * 128 + ((kb + bCol) ^ bXor);
                LDSM4(b[nj][0], b[nj][1], b[nj][2], b[nj][3], bd);
            }
            #pragma unroll
            for (int mi = 0; mi < 2; ++mi)
                #pragma unroll
                for (int nj = 0; nj < 4; ++nj) {
                    MMA16816(acc[mi][2 * nj],     a[mi], b[nj][0], b[nj][1]);
                    MMA16816(acc[mi][2 * nj + 1], a[mi], b[nj][2], b[nj][3]);
                }
        }
        __syncthreads();
    }

    // ---------------- epilogue: direct global stores + bias ----------------
    const int cr = lane >> 2;
    const int cc = (lane & 3) * 2;
    const int gn = n0 + warp_n * 64 + cc;

    float2 bb[8];
    #pragma unroll
    for (int t = 0; t < 8; ++t)
        bb[t] = *reinterpret_cast<const float2*>(bias + gn + t * 8);

    #pragma unroll
    for (int mi = 0; mi < 2; ++mi) {
        size_t gm = (size_t)(m0 + warp_m * 32 + mi * 16 + cr);
        float* p0 = out + gm * OFEAT + gn;
        float* p1 = p0 + (size_t)8 * OFEAT;
        #pragma unroll
        for (int t = 0; t < 8; ++t) {
            float2 v0 = make_float2(acc[mi][t][0] + bb[t].x, acc[mi][t][1] + bb[t].y);
            float2 v1 = make_float2(acc[mi][t][2] + bb[t].x, acc[mi][t][3] + bb[t].y);
            *reinterpret_cast<float2*>(p0 + t * 8) = v0;
            *reinterpret_cast<float2*>(p1 + t * 8) = v1;
        }
    }
}

// ------------------------- host launch -------------------------
extern "C" void kernel_launch(void* const* d_in, const int* in_sizes, int n_in,
                              void* d_out, int out_size) {
    const float* x    = (const float*)d_in[0];
    const float* p    = (const float*)d_in[1];
    const float* bias = (const float*)d_in[2];
    float* out        = (float*)d_out;
    (void)in_sizes; (void)n_in; (void)out_size;

    void *pxh = nullptr, *pwh = nullptr;
    cudaGetSymbolAddress(&pxh, g_xh);
    cudaGetSymbolAddress(&pwh, g_wh);

    cudaFuncSetAttribute(toep_gemm_kernel,
                         cudaFuncAttributeMaxDynamicSharedMemorySize, SMEM_TOTAL);

    // prep: x -> fp16, Toeplitz W -> fp16
    prep_x_kernel<<<BATCH_SZ * IFEAT / (256 * 8), 256>>>(x, (__half*)pxh);
    prep_w_kernel<<<OFEAT, 256>>>(p, (__half*)pwh);

    dim3 grid(OFEAT / BN, BATCH_SZ / BM);   // (16, 64)
    toep_gemm_kernel<<<grid, NTHREADS, SMEM_TOTAL>>>(
        (const __half*)pxh, (const __half*)pwh, bias, out);
}

// round 6
// speedup vs baseline: 1.0828x; 1.0828x over previous
#include <cuda_runtime.h>
#include <cuda.h>
#include <cstdint>

// ===========================================================================
// LinearToeplitz via FFT correlation.
// out[b,o] = sum_i x[b,i] * p[i + (O-1-o)] + bias[o],  B=8192, I=O=4096.
// N=8192 circular FFT (p padded by one zero => no wraparound for j<=4095).
// Two real rows packed per complex FFT: z = x_a + i*x_b.
//   c_a + i*c_b = IFFT_k( Z[(N-k)%N] * P[k] ),   out[b, O-1-j] = c[j] + bias.
// IFFT(W) = conj(FFT(conj(W)))/N.
// Stockham autosort FFT, radices [8,8,8,8,2], smem double buffer, pad-by-8.
// ===========================================================================

#define BATCH_SZ 8192
#define IFEAT    4096
#define OFEAT    4096
#define NFFT     8192
#define NTHREADS 512

// padded smem index: 1 extra float2 per 8 -> caps bank conflicts at 2-way
__device__ __forceinline__ int PHYS(int i) { return i + (i >> 3); }
#define BUF_F2 9216                        // PHYS(8191)=9214 < 9216
#define SMEM_TOTAL (2 * BUF_F2 * 8)        // 147456 bytes

// ------------------------- global tables -------------------------
__device__ float2 g_tw[NFFT];   // e^{-2*pi*i*k/N}
__device__ float2 g_P[NFFT];    // DFT of p padded to N

// ------------------------- complex helpers -------------------------
__device__ __forceinline__ float2 cmul(float2 a, float2 b) {
    return make_float2(a.x * b.x - a.y * b.y, a.x * b.y + a.y * b.x);
}
__device__ __forceinline__ float2 cadd(float2 a, float2 b) {
    return make_float2(a.x + b.x, a.y + b.y);
}
__device__ __forceinline__ float2 csub(float2 a, float2 b) {
    return make_float2(a.x - b.x, a.y - b.y);
}
// multiply by -i : (x,y) -> (y,-x)
__device__ __forceinline__ float2 cmni(float2 a) { return make_float2(a.y, -a.x); }

// In-place DFT-8 (natural order out), standard split-radix-2 style.
__device__ __forceinline__ void dft8(float2 v[8]) {
    const float S = 0.70710678118654752440f;
    float2 t0 = cadd(v[0], v[4]), t1 = csub(v[0], v[4]);
    float2 t2 = cadd(v[2], v[6]), t3 = cmni(csub(v[2], v[6]));
    float2 t4 = cadd(v[1], v[5]), t5 = csub(v[1], v[5]);
    float2 t6 = cadd(v[3], v[7]), t7 = cmni(csub(v[3], v[7]));
    float2 e0 = cadd(t0, t2), e1 = cadd(t1, t3), e2 = csub(t0, t2), e3 = csub(t1, t3);
    float2 o0 = cadd(t4, t6), o1 = cadd(t5, t7), o2 = csub(t4, t6), o3 = csub(t5, t7);
    o1 = cmul(o1, make_float2(S, -S));     // w8^1
    o2 = cmni(o2);                         // w8^2 = -i
    o3 = cmul(o3, make_float2(-S, -S));    // w8^3
    v[0] = cadd(e0, o0); v[4] = csub(e0, o0);
    v[1] = cadd(e1, o1); v[5] = csub(e1, o1);
    v[2] = cadd(e2, o2); v[6] = csub(e2, o2);
    v[3] = cadd(e3, o3); v[7] = csub(e3, o3);
}

// ------------------------- Stockham passes -------------------------
// radix-8 pass: v[r] = src[j + r*N/8]; v[r] *= w^r, w = e^{-2pi i (j%Ns)/(8 Ns)};
// dft8; dst[(j/Ns)*8Ns + j%Ns + r*Ns] = v[r].
template <int NS>
__device__ __forceinline__ void pass8(const float2* __restrict__ src,
                                      float2* __restrict__ dst, int tid) {
    #pragma unroll
    for (int b = 0; b < 2; ++b) {
        int j = tid + b * NTHREADS;            // j in [0, 1024)
        float2 v[8];
        #pragma unroll
        for (int r = 0; r < 8; ++r) v[r] = src[PHYS(j + r * (NFFT / 8))];
        if (NS > 1) {
            int tb = (j & (NS - 1)) * (NFFT / (NS * 8));
            float2 w1 = g_tw[tb];
            float2 w = w1;
            #pragma unroll
            for (int r = 1; r < 8; ++r) { v[r] = cmul(v[r], w); w = cmul(w, w1); }
        }
        dft8(v);
        int idxD = (j / NS) * (NS * 8) + (j & (NS - 1));
        #pragma unroll
        for (int r = 0; r < 8; ++r) dst[PHYS(idxD + r * NS)] = v[r];
    }
}

// final radix-2 pass, Ns = 4096
__device__ __forceinline__ void pass2(const float2* __restrict__ src,
                                      float2* __restrict__ dst, int tid) {
    #pragma unroll
    for (int s = 0; s < 8; ++s) {
        int j = tid + s * NTHREADS;            // j in [0, 4096)
        float2 v0 = src[PHYS(j)];
        float2 v1 = src[PHYS(j + 4096)];
        v1 = cmul(v1, g_tw[j]);                // w = e^{-2pi i j/8192}
        dst[PHYS(j)]        = cadd(v0, v1);
        dst[PHYS(j + 4096)] = csub(v0, v1);
    }
}

__device__ __forceinline__ void fft8192(float2* A, float2* B, int tid) {
    pass8<1>(A, B, tid);   __syncthreads();
    pass8<8>(B, A, tid);   __syncthreads();
    pass8<64>(A, B, tid);  __syncthreads();
    pass8<512>(B, A, tid); __syncthreads();
    pass2(A, B, tid);      __syncthreads();    // result in B
}

// ------------------------- prep kernels -------------------------
__global__ void prep_tw_kernel() {
    int k = blockIdx.x * 256 + threadIdx.x;
    float s, c;
    sincospif(-(float)k / 4096.0f, &s, &c);    // angle = -2*pi*k/8192
    g_tw[k] = make_float2(c, s);
}

// naive DFT of p (length 8191, zero-padded to 8192): one block per k.
__global__ void prep_P_kernel(const float* __restrict__ p) {
    int k = blockIdx.x;
    int t = threadIdx.x;
    float2 acc = make_float2(0.f, 0.f);
    for (int m = t; m < NFFT - 1; m += 128) {
        float pv = __ldg(p + m);
        int idx = (int)(((unsigned)k * (unsigned)m) & (NFFT - 1));
        float2 w = g_tw[idx];
        acc.x += pv * w.x;
        acc.y += pv * w.y;
    }
    __shared__ float2 red[128];
    red[t] = acc;
    __syncthreads();
    for (int s = 64; s > 0; s >>= 1) {
        if (t < s) { red[t].x += red[t + s].x; red[t].y += red[t + s].y; }
        __syncthreads();
    }
    if (t == 0) g_P[k] = red[0];
}

// ------------------------- main kernel -------------------------
__global__ void __launch_bounds__(NTHREADS, 1) fft_toeplitz_kernel(
    const float* __restrict__ x,
    const float* __restrict__ bias,
    float* __restrict__ out)
{
    extern __shared__ __align__(16) float2 sm[];
    float2* A = sm;
    float2* B = sm + BUF_F2;
    const int tid = threadIdx.x;
    const size_t b0 = (size_t)blockIdx.x * 2;

    const float* xa = x + b0 * IFEAT;
    const float* xb = xa + IFEAT;

    // load + pack + zero-pad
    for (int i = tid; i < IFEAT; i += NTHREADS)
        A[PHYS(i)] = make_float2(xa[i], xb[i]);
    for (int i = IFEAT + tid; i < NFFT; i += NTHREADS)
        A[PHYS(i)] = make_float2(0.f, 0.f);
    __syncthreads();

    // forward FFT: Z in B
    fft8192(A, B, tid);

    // pointwise: U[k] = conj( Z[(N-k)%N] * P[k] )  -> A
    for (int k = tid; k < NFFT; k += NTHREADS) {
        int rev = (NFFT - k) & (NFFT - 1);
        float2 Z = B[PHYS(rev)];
        float2 W = cmul(Z, g_P[k]);
        A[PHYS(k)] = make_float2(W.x, -W.y);
    }
    __syncthreads();

    // second FFT: V = FFT(U) in B;  c = conj(V)/N
    fft8192(A, B, tid);

    const float inv = 1.0f / (float)NFFT;
    float* o0 = out + b0 * OFEAT;
    float* o1 = o0 + OFEAT;
    for (int j = tid; j < OFEAT; j += NTHREADS) {
        float2 V = B[PHYS(j)];
        int o = OFEAT - 1 - j;
        float bb = __ldg(bias + o);
        o0[o] =  V.x * inv + bb;
        o1[o] = -V.y * inv + bb;
    }
}

// ------------------------- host launch -------------------------
extern "C" void kernel_launch(void* const* d_in, const int* in_sizes, int n_in,
                              void* d_out, int out_size) {
    const float* x    = (const float*)d_in[0];
    const float* p    = (const float*)d_in[1];
    const float* bias = (const float*)d_in[2];
    float* out        = (float*)d_out;
    (void)in_sizes; (void)n_in; (void)out_size;

    cudaFuncSetAttribute(fft_toeplitz_kernel,
                         cudaFuncAttributeMaxDynamicSharedMemorySize, SMEM_TOTAL);

    prep_tw_kernel<<<NFFT / 256, 256>>>();
    prep_P_kernel<<<NFFT, 128>>>(p);
    fft_toeplitz_kernel<<<BATCH_SZ / 2, NTHREADS, SMEM_TOTAL>>>(x, bias, out);
}

// round 7
// speedup vs baseline: 1.6894x; 1.5603x over previous
#include <cuda_runtime.h>
#include <cuda.h>
#include <cstdint>

// ===========================================================================
// LinearToeplitz via FFT correlation, in-place DIF->DIT, 2 CTAs/SM.
// out[b,o] = sum_i x[b,i] * p[i + (O-1-o)] + bias[o],  B=8192, I=O=4096.
// corr = (1/N) * FFT( FFT(z) .* conj(P) ),  z = x_a + i*x_b,  P = FFT(p_pad).
// DIF (natural -> digit-rev) then DIT (= DIF^T, digit-rev -> natural): the
// pointwise multiply happens in the digit-reversed domain; prep runs the SAME
// DIF on p so slots align automatically.
// ===========================================================================

#define BATCH_SZ 8192
#define IFEAT    4096
#define OFEAT    4096
#define NFFT     8192
#define NTHREADS 512

__device__ __forceinline__ int PHYS(int i) { return i + (i >> 3); }
#define BUF_F2 9216
#define SMEM_TOTAL (BUF_F2 * 8)            // 73728 bytes -> 2 CTAs/SM

// ------------------------- global tables -------------------------
__device__ float2 g_tw[NFFT];   // e^{-2*pi*i*k/N}
__device__ float2 g_P[NFFT];    // conj(DIF(p_pad)) in DIF slot order

// ------------------------- complex helpers -------------------------
__device__ __forceinline__ float2 cmul(float2 a, float2 b) {
    return make_float2(a.x * b.x - a.y * b.y, a.x * b.y + a.y * b.x);
}
__device__ __forceinline__ float2 cadd(float2 a, float2 b) {
    return make_float2(a.x + b.x, a.y + b.y);
}
__device__ __forceinline__ float2 csub(float2 a, float2 b) {
    return make_float2(a.x - b.x, a.y - b.y);
}
__device__ __forceinline__ float2 cmni(float2 a) { return make_float2(a.y, -a.x); }

// forward DFT-8 (w8 = e^{-2pi i/8}), verified in round 6.
__device__ __forceinline__ void dft8(float2 v[8]) {
    const float S = 0.70710678118654752440f;
    float2 t0 = cadd(v[0], v[4]), t1 = csub(v[0], v[4]);
    float2 t2 = cadd(v[2], v[6]), t3 = cmni(csub(v[2], v[6]));
    float2 t4 = cadd(v[1], v[5]), t5 = csub(v[1], v[5]);
    float2 t6 = cadd(v[3], v[7]), t7 = cmni(csub(v[3], v[7]));
    float2 e0 = cadd(t0, t2), e1 = cadd(t1, t3), e2 = csub(t0, t2), e3 = csub(t1, t3);
    float2 o0 = cadd(t4, t6), o1 = cadd(t5, t7), o2 = csub(t4, t6), o3 = csub(t5, t7);
    o1 = cmul(o1, make_float2(S, -S));
    o2 = cmni(o2);
    o3 = cmul(o3, make_float2(-S, -S));
    v[0] = cadd(e0, o0); v[4] = csub(e0, o0);
    v[1] = cadd(e1, o1); v[5] = csub(e1, o1);
    v[2] = cadd(e2, o2); v[6] = csub(e2, o2);
    v[3] = cadd(e3, o3); v[7] = csub(e3, o3);
}

// multiply v[1..7] by w^r, w = g_tw[idx] (idx may be 0 -> skip)
__device__ __forceinline__ void twmul(float2 v[8], int idx) {
    if (idx) {
        float2 w1 = g_tw[idx], w2 = g_tw[2 * idx], w4 = g_tw[4 * idx];
        float2 w3 = cmul(w1, w2), w5 = cmul(w1, w4);
        float2 w6 = cmul(w2, w4), w7 = cmul(w3, w4);
        v[1] = cmul(v[1], w1); v[2] = cmul(v[2], w2); v[3] = cmul(v[3], w3);
        v[4] = cmul(v[4], w4); v[5] = cmul(v[5], w5); v[6] = cmul(v[6], w6);
        v[7] = cmul(v[7], w7);
    }
}

// In-place radix-8 pass at span S. PRE=true: twiddle before dft (DIT);
// PRE=false: twiddle after dft (DIF).
template <int S, bool PRE>
__device__ __forceinline__ void pass8_ip(float2* a, int tid) {
    #pragma unroll 1
    for (int b = 0; b < 2; ++b) {
        int w = tid + b * NTHREADS;               // [0, 1024)
        int q = w & (S - 1);
        int base = ((w & ~(S - 1)) << 3) + q;     // (w/S)*8S + q
        int idx = q * (NFFT / (8 * S));
        float2 v[8];
        #pragma unroll
        for (int r = 0; r < 8; ++r) v[r] = a[PHYS(base + r * S)];
        if (PRE) twmul(v, idx);
        dft8(v);
        if (!PRE) twmul(v, idx);
        #pragma unroll
        for (int r = 0; r < 8; ++r) a[PHYS(base + r * S)] = v[r];
    }
}

// radix-2 at S=1 (DIF-last == DIT-first, no twiddle)
__device__ __forceinline__ void pass2_ip(float2* a, int tid) {
    #pragma unroll 1
    for (int s = 0; s < 8; ++s) {
        int m = tid + s * NTHREADS;               // [0, 4096)
        int i0 = PHYS(2 * m), i1 = PHYS(2 * m + 1);
        float2 e0 = a[i0], e1 = a[i1];
        a[i0] = cadd(e0, e1);
        a[i1] = csub(e0, e1);
    }
}

// ------------------------- prep kernels -------------------------
__global__ void prep_tw_kernel() {
    int k = blockIdx.x * 256 + threadIdx.x;
    float s, c;
    sincospif(-(float)k / 4096.0f, &s, &c);
    g_tw[k] = make_float2(c, s);
}

// Run the SAME DIF on p_pad (one CTA), store conj in slot order.
__global__ void __launch_bounds__(NTHREADS, 2) prep_P_kernel(const float* __restrict__ p) {
    extern __shared__ __align__(16) float2 a[];
    const int tid = threadIdx.x;
    for (int i = tid; i < NFFT; i += NTHREADS) {
        float v = (i < NFFT - 1) ? __ldg(p + i) : 0.f;
        a[PHYS(i)] = make_float2(v, 0.f);
    }
    __syncthreads();
    pass8_ip<1024, false>(a, tid); __syncthreads();
    pass8_ip<128,  false>(a, tid); __syncthreads();
    pass8_ip<16,   false>(a, tid); __syncthreads();
    pass8_ip<2,    false>(a, tid); __syncthreads();
    pass2_ip(a, tid);              __syncthreads();
    for (int i = tid; i < NFFT; i += NTHREADS) {
        float2 v = a[PHYS(i)];
        g_P[i] = make_float2(v.x, -v.y);
    }
}

// ------------------------- main kernel -------------------------
__global__ void __launch_bounds__(NTHREADS, 2) fft_toeplitz_kernel(
    const float* __restrict__ x,
    const float* __restrict__ bias,
    float* __restrict__ out)
{
    extern __shared__ __align__(16) float2 a[];
    const int tid = threadIdx.x;
    const size_t b0 = (size_t)blockIdx.x * 2;
    const float* xa = x + b0 * IFEAT;
    const float* xb = xa + IFEAT;

    // ---- DIF pass S=1024 fused with global load (upper half = zero pad) ----
    #pragma unroll 1
    for (int b = 0; b < 2; ++b) {
        int w = tid + b * NTHREADS;               // q = w
        float2 v[8];
        #pragma unroll
        for (int r = 0; r < 4; ++r)
            v[r] = make_float2(__ldg(xa + w + r * 1024), __ldg(xb + w + r * 1024));
        #pragma unroll
        for (int r = 4; r < 8; ++r) v[r] = make_float2(0.f, 0.f);
        dft8(v);
        twmul(v, w);                               // idx = q*N/(8S) = w
        #pragma unroll
        for (int r = 0; r < 8; ++r) a[PHYS(w + r * 1024)] = v[r];
    }
    __syncthreads();

    pass8_ip<128, false>(a, tid); __syncthreads();
    pass8_ip<16,  false>(a, tid); __syncthreads();
    pass8_ip<2,   false>(a, tid); __syncthreads();

    // ---- fused: DIF radix-2 + pointwise (.* g_P) + DIT radix-2 ----
    #pragma unroll 1
    for (int s = 0; s < 8; ++s) {
        int m = tid + s * NTHREADS;
        int i0 = PHYS(2 * m), i1 = PHYS(2 * m + 1);
        float2 e0 = a[i0], e1 = a[i1];
        float2 f0 = cadd(e0, e1), f1 = csub(e0, e1);
        float4 pp = *reinterpret_cast<const float4*>(g_P + 2 * m);
        f0 = cmul(f0, make_float2(pp.x, pp.y));
        f1 = cmul(f1, make_float2(pp.z, pp.w));
        a[i0] = cadd(f0, f1);
        a[i1] = csub(f0, f1);
    }
    __syncthreads();

    pass8_ip<2,   true>(a, tid); __syncthreads();
    pass8_ip<16,  true>(a, tid); __syncthreads();
    pass8_ip<128, true>(a, tid); __syncthreads();

    // ---- DIT pass S=1024 fused with global store (keep j < 4096) ----
    const float inv = 1.0f / (float)NFFT;
    float* o0 = out + b0 * OFEAT;
    float* o1 = o0 + OFEAT;
    #pragma unroll 1
    for (int b = 0; b < 2; ++b) {
        int w = tid + b * NTHREADS;
        float2 v[8];
        #pragma unroll
        for (int r = 0; r < 8; ++r) v[r] = a[PHYS(w + r * 1024)];
        twmul(v, w);
        dft8(v);
        #pragma unroll
        for (int r = 0; r < 4; ++r) {
            int j = w + r * 1024;                  // natural output index
            int o = OFEAT - 1 - j;
            float bb = __ldg(bias + o);
            o0[o] = v[r].x * inv + bb;
            o1[o] = v[r].y * inv + bb;
        }
    }
}

// ------------------------- host launch -------------------------
extern "C" void kernel_launch(void* const* d_in, const int* in_sizes, int n_in,
                              void* d_out, int out_size) {
    const float* x    = (const float*)d_in[0];
    const float* p    = (const float*)d_in[1];
    const float* bias = (const float*)d_in[2];
    float* out        = (float*)d_out;
    (void)in_sizes; (void)n_in; (void)out_size;

    cudaFuncSetAttribute(prep_P_kernel,
                         cudaFuncAttributeMaxDynamicSharedMemorySize, SMEM_TOTAL);
    cudaFuncSetAttribute(fft_toeplitz_kernel,
                         cudaFuncAttributeMaxDynamicSharedMemorySize, SMEM_TOTAL);

    prep_tw_kernel<<<NFFT / 256, 256>>>();
    prep_P_kernel<<<1, NTHREADS, SMEM_TOTAL>>>(p);
    fft_toeplitz_kernel<<<BATCH_SZ / 2, NTHREADS, SMEM_TOTAL>>>(x, bias, out);
}